// round 14
// baseline (speedup 1.0000x reference)
#include <cuda_runtime.h>
#include <cuda_fp16.h>
#include <cstdint>
#include <math.h>

#define N_    8
#define C_    256
#define H_    64
#define W_    64
#define K_    9
#define P_    4096          // 64*64
#define CK_   2304          // C_*K_
#define COUT_ 256
#define NCHUNK 36           // CK_/64

// ------------------------------- scratch ------------------------------------
__device__ __half g_xh[(size_t)N_ * P_ * C_];     // x NHWC fp16
__device__ __half g_ch[(size_t)N_ * P_ * CK_];    // cols, K-major [n][p][k*256+c]
__device__ __half g_wh[COUT_ * CK_];              // weights [cout][k*256+c]

// ---------------- small PTX helpers (family-agnostic only) ------------------
__device__ __forceinline__ uint32_t smem_to_u32(const void* p) {
    uint32_t a;
    asm("{ .reg .u64 t; cvta.to.shared.u64 t, %1; cvt.u32.u64 %0, t; }"
        : "=r"(a) : "l"(p));
    return a;
}
__device__ __forceinline__ void cp16(uint32_t dst, const void* src) {
    asm volatile("cp.async.cg.shared.global [%0], [%1], 16;"
                 :: "r"(dst), "l"(src));
}
__device__ __forceinline__ void cp_commit() {
    asm volatile("cp.async.commit_group;" ::: "memory");
}
template <int NN>
__device__ __forceinline__ void cp_wait() {
    asm volatile("cp.async.wait_group %0;" :: "n"(NN) : "memory");
}
__device__ __forceinline__ void ldsm4(uint32_t* r, uint32_t addr) {
    asm volatile("ldmatrix.sync.aligned.m8n8.x4.shared.b16 {%0,%1,%2,%3}, [%4];"
        : "=r"(r[0]), "=r"(r[1]), "=r"(r[2]), "=r"(r[3]) : "r"(addr));
}
__device__ __forceinline__ void mma16816h(float* d, const uint32_t* a,
                                          uint32_t b0, uint32_t b1) {
    asm volatile("mma.sync.aligned.m16n8k16.row.col.f32.f16.f16.f32 "
        "{%0,%1,%2,%3}, {%4,%5,%6,%7}, {%8,%9}, {%0,%1,%2,%3};"
        : "+f"(d[0]), "+f"(d[1]), "+f"(d[2]), "+f"(d[3])
        : "r"(a[0]), "r"(a[1]), "r"(a[2]), "r"(a[3]), "r"(b0), "r"(b1));
}

// ---------------------------------------------------------------------------
// Kernel -1: x NCHW fp32 -> NHWC fp16 (smem transpose)
// ---------------------------------------------------------------------------
__global__ __launch_bounds__(256)
void nhwc_k(const float* __restrict__ x) {
    __shared__ float sm[64][33];
    const int n  = blockIdx.z;
    const int c0 = blockIdx.y * 64;
    const int s0 = blockIdx.x * 32;
    const int tx = threadIdx.x & 31;
    const int ty = threadIdx.x >> 5;

    #pragma unroll
    for (int i = 0; i < 8; ++i) {
        int c = i * 8 + ty;
        sm[c][tx] = x[((size_t)n * C_ + c0 + c) * P_ + s0 + tx];
    }
    __syncthreads();
    #pragma unroll
    for (int i = 0; i < 4; ++i) {
        int s = i * 8 + ty;
        __half2 h = __floats2half2_rn(sm[2 * tx][s], sm[2 * tx + 1][s]);
        *(__half2*)(g_xh + ((size_t)(n * P_ + s0 + s)) * C_ + c0 + 2 * tx) = h;
    }
}

// ---------------------------------------------------------------------------
// Kernel 0: weight convert + reorder
// ---------------------------------------------------------------------------
__global__ void wsplit_k(const float* __restrict__ w) {
    int o = blockIdx.x * 256 + threadIdx.x;
    if (o >= COUT_ * CK_) return;
    int cout = o / CK_;
    int r    = o % CK_;
    int k    = r >> 8;
    int c    = r & 255;
    g_wh[o] = __float2half_rn(w[(size_t)cout * CK_ + c * 9 + k]);
}

// ---------------------------------------------------------------------------
// Kernel 1: deformable im2col, ONE batch per launch (MLP-8 variant)
// ---------------------------------------------------------------------------
struct Corners {
    float w00, w01, w10, w11;
    const __half *c00, *c01, *c10, *c11;
};

__device__ __forceinline__ Corners corner_params(
    const float* __restrict__ ob, const __half* __restrict__ xb,
    int ky, int kx, int p)
{
    const int ho = p >> 6, wo = p & 63;
    float py = (float)(ho - 1 + ky) + __ldg(ob + p);
    float px = (float)(wo - 1 + kx) + __ldg(ob + P_ + p);

    float y0f = floorf(py), x0f = floorf(px);
    float ly = py - y0f, lx = px - x0f;
    float hy = 1.0f - ly, hx = 1.0f - lx;
    int y0 = (int)y0f, x0 = (int)x0f;
    int y1 = y0 + 1,   x1 = x0 + 1;

    bool vy0 = ((unsigned)y0 < (unsigned)H_);
    bool vy1 = ((unsigned)y1 < (unsigned)H_);
    bool vx0 = ((unsigned)x0 < (unsigned)W_);
    bool vx1 = ((unsigned)x1 < (unsigned)W_);

    int cy0 = min(max(y0, 0), H_ - 1);
    int cy1 = min(max(y1, 0), H_ - 1);
    int cx0 = min(max(x0, 0), W_ - 1);
    int cx1 = min(max(x1, 0), W_ - 1);

    Corners cp;
    cp.w00 = (vy0 && vx0) ? hy * hx : 0.0f;
    cp.w01 = (vy0 && vx1) ? hy * lx : 0.0f;
    cp.w10 = (vy1 && vx0) ? ly * hx : 0.0f;
    cp.w11 = (vy1 && vx1) ? ly * lx : 0.0f;
    cp.c00 = xb + (size_t)(cy0 * W_ + cx0) * C_;
    cp.c01 = xb + (size_t)(cy0 * W_ + cx1) * C_;
    cp.c10 = xb + (size_t)(cy1 * W_ + cx0) * C_;
    cp.c11 = xb + (size_t)(cy1 * W_ + cx1) * C_;
    return cp;
}

__device__ __forceinline__ uint4 bilin_combine(const Corners& cp,
        uint4 a00, uint4 a01, uint4 a10, uint4 a11)
{
    union { __half2 h[4]; uint4 v; } o;
    const __half2* h00 = (const __half2*)&a00;
    const __half2* h01 = (const __half2*)&a01;
    const __half2* h10 = (const __half2*)&a10;
    const __half2* h11 = (const __half2*)&a11;
    #pragma unroll
    for (int j = 0; j < 4; ++j) {
        float2 f00 = __half22float2(h00[j]);
        float2 f01 = __half22float2(h01[j]);
        float2 f10 = __half22float2(h10[j]);
        float2 f11 = __half22float2(h11[j]);
        float2 r;
        r.x = cp.w00 * f00.x + cp.w01 * f01.x + cp.w10 * f10.x + cp.w11 * f11.x;
        r.y = cp.w00 * f00.y + cp.w01 * f01.y + cp.w10 * f10.y + cp.w11 * f11.y;
        o.h[j] = __float22half2_rn(r);
    }
    return o.v;
}

__global__ __launch_bounds__(256)
void im2col_k(const float* __restrict__ off, int n)
{
    const int lane = threadIdx.x & 31;
    const int wib  = threadIdx.x >> 5;        // 0..7
    const int bid  = blockIdx.x;              // K*P/16 = 2304 blocks
    const int p0   = (bid & 255) * 16;
    const int k    = bid >> 8;                // 0..8
    const int ky   = k / 3, kx = k % 3;

    const int pA = p0 + wib;
    const int pB = p0 + 8 + wib;

    const float* ob = off + ((size_t)n * (2 * K_) + k * 2) * P_;
    const __half* xb = g_xh + ((size_t)n << 20);   // n * P_ * C_

    Corners ca = corner_params(ob, xb, ky, kx, pA);
    Corners cb = corner_params(ob, xb, ky, kx, pB);

    uint4 a00 = __ldg((const uint4*)ca.c00 + lane);
    uint4 a01 = __ldg((const uint4*)ca.c01 + lane);
    uint4 a10 = __ldg((const uint4*)ca.c10 + lane);
    uint4 a11 = __ldg((const uint4*)ca.c11 + lane);
    uint4 b00 = __ldg((const uint4*)cb.c00 + lane);
    uint4 b01 = __ldg((const uint4*)cb.c01 + lane);
    uint4 b10 = __ldg((const uint4*)cb.c10 + lane);
    uint4 b11 = __ldg((const uint4*)cb.c11 + lane);

    uint4 ra = bilin_combine(ca, a00, a01, a10, a11);
    uint4 rb = bilin_combine(cb, b00, b01, b10, b11);

    *(uint4*)(g_ch + ((size_t)(n * P_ + pA)) * CK_ + k * 256 + lane * 8) = ra;
    *(uint4*)(g_ch + ((size_t)(n * P_ + pB)) * CK_ + k * 256 + lane * 8) = rb;
}

// ---------------------------------------------------------------------------
// Kernel 2: fp16 mma.sync GEMM, ONE batch per launch (R10-exact body).
// CTA tile 128 cout x 128 pixels, 8 warps of 64x32.
// K-chunk 64, 3-stage cp.async pipeline, one barrier per chunk.
// 110.6 KB smem, 2 CTAs/SM.
// ---------------------------------------------------------------------------
#define PITCH     144           // 128B data + 16B pad -> conflict-free ldmatrix
#define A_OFF     0
#define B_OFF     18432         // A: 128 rows * 144
#define STAGE     36864         // + B: 128 rows * 144
#define NSTAGE    3
#define SMEM_TOTAL (NSTAGE * STAGE)   // 110592 B

__device__ __forceinline__ void load_stage(uint32_t st, int chunk,
                                           int cout0, int n, int p0, int tid)
{
    const size_t cb = (size_t)chunk * 128;       // byte offset in 4608 B row
    #pragma unroll
    for (int i = 0; i < 8; ++i) {
        int idx = tid + i * 256;                 // 0..2047
        int region = idx >> 10;                  // 0=A(weights), 1=B(cols)
        int r   = idx & 1023;
        int row = r >> 3;                        // 0..127
        int c16 = (r & 7) * 16;                  // 0..112
        if (region == 0) {
            cp16(st + A_OFF + row * PITCH + c16,
                 (const char*)g_wh + (size_t)(cout0 + row) * (CK_ * 2) + cb + c16);
        } else {
            cp16(st + B_OFF + row * PITCH + c16,
                 (const char*)g_ch + ((size_t)(n * P_ + p0 + row)) * (CK_ * 2) + cb + c16);
        }
    }
}

__global__ __launch_bounds__(256, 2)
void gemm_k(const float* __restrict__ bias, float* __restrict__ out, int n)
{
    extern __shared__ __align__(128) char smem[];
    const uint32_t sb = smem_to_u32(smem);

    const int tid    = threadIdx.x;
    const int lane   = tid & 31;
    const int wid    = tid >> 5;
    const int warp_m = wid & 1;       // 64-cout half
    const int warp_n = wid >> 1;      // 32-pixel quarter

    const int cout0 = blockIdx.x * 128;
    const int p0    = blockIdx.y * 128;

    float d[4][4][4];
    #pragma unroll
    for (int mi = 0; mi < 4; ++mi)
        #pragma unroll
        for (int ni = 0; ni < 4; ++ni)
            #pragma unroll
            for (int j = 0; j < 4; ++j) d[mi][ni][j] = 0.0f;

    #pragma unroll
    for (int s = 0; s < NSTAGE - 1; ++s) {
        load_stage(sb + s * STAGE, s, cout0, n, p0, tid);
        cp_commit();
    }

    const int a_row = (lane & 15);
    const int a_c16 = (lane >> 4) << 4;
    const int b_row = (lane & 7) + ((lane >> 4) << 3);
    const int b_c16 = ((lane >> 3) & 1) << 4;

    int stage_id = 0;   // ring index of current chunk's stage
    for (int c = 0; c < NCHUNK; ++c) {
        cp_wait<NSTAGE - 2>();
        __syncthreads();

        if (c + NSTAGE - 1 < NCHUNK) {
            int pf = stage_id + (NSTAGE - 1);
            if (pf >= NSTAGE) pf -= NSTAGE;
            load_stage(sb + pf * STAGE, c + NSTAGE - 1, cout0, n, p0, tid);
        }
        cp_commit();

        const uint32_t st = sb + stage_id * STAGE;
        if (++stage_id == NSTAGE) stage_id = 0;

        #pragma unroll
        for (int s = 0; s < 4; ++s) {           // four k16 steps per chunk
            uint32_t ah[4][4];
            #pragma unroll
            for (int mi = 0; mi < 4; ++mi)
                ldsm4(ah[mi], st + A_OFF
                      + (warp_m * 64 + mi * 16 + a_row) * PITCH + s * 32 + a_c16);
            uint32_t bhf[2][4];
            #pragma unroll
            for (int np = 0; np < 2; ++np)
                ldsm4(bhf[np], st + B_OFF
                      + (warp_n * 32 + np * 16 + b_row) * PITCH + s * 32 + b_c16);
            #pragma unroll
            for (int mi = 0; mi < 4; ++mi)
                #pragma unroll
                for (int ni = 0; ni < 4; ++ni) {
                    const int np = ni >> 1, sub = (ni & 1) * 2;
                    mma16816h(d[mi][ni], ah[mi], bhf[np][sub], bhf[np][sub + 1]);
                }
        }
    }

    // epilogue
    const int gr = lane >> 2;
    const int gc = (lane & 3) * 2;
    #pragma unroll
    for (int mi = 0; mi < 4; ++mi) {
        const int cout = cout0 + warp_m * 64 + mi * 16 + gr;
        const float bv0 = __ldg(bias + cout);
        const float bv1 = __ldg(bias + cout + 8);
        float* base = out + ((size_t)n * COUT_ + cout) * P_;
        #pragma unroll
        for (int ni = 0; ni < 4; ++ni) {
            const int px = p0 + warp_n * 32 + ni * 8 + gc;
            float2 v0 = make_float2(d[mi][ni][0] + bv0, d[mi][ni][1] + bv0);
            float2 v1 = make_float2(d[mi][ni][2] + bv1, d[mi][ni][3] + bv1);
            *(float2*)(base + px)          = v0;
            *(float2*)(base + 8 * P_ + px) = v1;
        }
    }
}

// ---------------------------------------------------------------------------
extern "C" void kernel_launch(void* const* d_in, const int* in_sizes, int n_in,
                              void* d_out, int out_size)
{
    const float* x    = (const float*)d_in[0];
    const float* off  = (const float*)d_in[1];
    const float* wgt  = (const float*)d_in[2];
    const float* bias = (const float*)d_in[3];
    float* out = (float*)d_out;

    // one-time resources (created on the uncaptured correctness call)
    static bool init_done = false;
    static cudaStream_t s1;
    static cudaEvent_t e_root, e_nhwc, e_col[N_];
    if (!init_done) {
        cudaFuncSetAttribute(gemm_k, cudaFuncAttributeMaxDynamicSharedMemorySize,
                             SMEM_TOTAL);
        cudaStreamCreateWithFlags(&s1, cudaStreamNonBlocking);
        cudaEventCreateWithFlags(&e_root, cudaEventDisableTiming);
        cudaEventCreateWithFlags(&e_nhwc, cudaEventDisableTiming);
        for (int n = 0; n < N_; ++n)
            cudaEventCreateWithFlags(&e_col[n], cudaEventDisableTiming);
        init_done = true;
    }

    // fork s1 off the main (captured) stream
    cudaEventRecord(e_root, 0);
    cudaStreamWaitEvent(s1, e_root, 0);

    // wsplit (s1) runs concurrently with nhwc (main)
    wsplit_k<<<(COUT_ * CK_ + 255) / 256, 256, 0, s1>>>(wgt);
    dim3 tgrid(P_ / 32, C_ / 64, N_);       // (128, 4, 8)
    nhwc_k<<<tgrid, 256>>>(x);

    // im2col per batch on s1 (after nhwc)
    cudaEventRecord(e_nhwc, 0);
    cudaStreamWaitEvent(s1, e_nhwc, 0);
    for (int n = 0; n < N_; ++n) {
        im2col_k<<<K_ * P_ / 16, 256, 0, s1>>>(off, n);
        cudaEventRecord(e_col[n], s1);
    }

    // gemm per batch on main stream, each gated only on its own cols
    dim3 ggrid(COUT_ / 128, P_ / 128, 1);   // (2, 32)
    for (int n = 0; n < N_; ++n) {
        cudaStreamWaitEvent(0, e_col[n], 0);
        gemm_k<<<ggrid, 256, SMEM_TOTAL>>>(bias, out, n);
    }
}

// round 15
// speedup vs baseline: 2.0618x; 2.0618x over previous
#include <cuda_runtime.h>
#include <cuda_fp16.h>
#include <cstdint>
#include <math.h>

#define N_    8
#define C_    256
#define H_    64
#define W_    64
#define K_    9
#define P_    4096          // 64*64
#define CK_   2304          // C_*K_
#define COUT_ 256
#define NCHUNK 36           // CK_/64

// ------------------------------- scratch ------------------------------------
__device__ __half g_xh[(size_t)N_ * P_ * C_];     // x NHWC fp16
__device__ __half g_ch[(size_t)N_ * P_ * CK_];    // cols, K-major [n][p][k*256+c]
__device__ __half g_wh[COUT_ * CK_];              // weights [cout][k*256+c]

// ---------------- small PTX helpers (family-agnostic only) ------------------
__device__ __forceinline__ uint32_t smem_to_u32(const void* p) {
    uint32_t a;
    asm("{ .reg .u64 t; cvta.to.shared.u64 t, %1; cvt.u32.u64 %0, t; }"
        : "=r"(a) : "l"(p));
    return a;
}
__device__ __forceinline__ void cp16(uint32_t dst, const void* src) {
    asm volatile("cp.async.cg.shared.global [%0], [%1], 16;"
                 :: "r"(dst), "l"(src));
}
__device__ __forceinline__ void cp_commit() {
    asm volatile("cp.async.commit_group;" ::: "memory");
}
template <int NN>
__device__ __forceinline__ void cp_wait() {
    asm volatile("cp.async.wait_group %0;" :: "n"(NN) : "memory");
}
__device__ __forceinline__ void ldsm4(uint32_t* r, uint32_t addr) {
    asm volatile("ldmatrix.sync.aligned.m8n8.x4.shared.b16 {%0,%1,%2,%3}, [%4];"
        : "=r"(r[0]), "=r"(r[1]), "=r"(r[2]), "=r"(r[3]) : "r"(addr));
}
__device__ __forceinline__ void mma16816h(float* d, const uint32_t* a,
                                          uint32_t b0, uint32_t b1) {
    asm volatile("mma.sync.aligned.m16n8k16.row.col.f32.f16.f16.f32 "
        "{%0,%1,%2,%3}, {%4,%5,%6,%7}, {%8,%9}, {%0,%1,%2,%3};"
        : "+f"(d[0]), "+f"(d[1]), "+f"(d[2]), "+f"(d[3])
        : "r"(a[0]), "r"(a[1]), "r"(a[2]), "r"(a[3]), "r"(b0), "r"(b1));
}

// ---------------------------------------------------------------------------
// Kernel P: fused prep. Blocks [0, 4096): x NCHW fp32 -> NHWC fp16 transpose.
// Blocks [4096, 6400): weight convert + reorder. Independent roles co-scheduled
// so the ALU-light wsplit hides inside nhwc's DRAM stalls.
// ---------------------------------------------------------------------------
__global__ __launch_bounds__(256)
void prep_k(const float* __restrict__ x, const float* __restrict__ w) {
    const int bid = blockIdx.x;
    if (bid < 4096) {                    // ---- nhwc transpose ----
        __shared__ float sm[64][33];
        const int s0 = (bid & 127) * 32;
        const int c0 = ((bid >> 7) & 3) * 64;
        const int n  = bid >> 9;
        const int tx = threadIdx.x & 31;
        const int ty = threadIdx.x >> 5;

        #pragma unroll
        for (int i = 0; i < 8; ++i) {
            int c = i * 8 + ty;
            sm[c][tx] = x[((size_t)n * C_ + c0 + c) * P_ + s0 + tx];
        }
        __syncthreads();
        #pragma unroll
        for (int i = 0; i < 4; ++i) {
            int s = i * 8 + ty;
            __half2 h = __floats2half2_rn(sm[2 * tx][s], sm[2 * tx + 1][s]);
            *(__half2*)(g_xh + ((size_t)(n * P_ + s0 + s)) * C_ + c0 + 2 * tx) = h;
        }
    } else {                             // ---- weight convert + reorder ----
        int o = (bid - 4096) * 256 + threadIdx.x;
        if (o >= COUT_ * CK_) return;
        int cout = o / CK_;
        int r    = o % CK_;
        int k    = r >> 8;
        int c    = r & 255;
        g_wh[o] = __float2half_rn(w[(size_t)cout * CK_ + c * 9 + k]);
    }
}

// ---------------------------------------------------------------------------
// Kernel 1: deformable im2col (batched, MLP-8: warp handles 2 pixels,
// all 8 corner LDG.128 in flight before combining).
// ---------------------------------------------------------------------------
struct Corners {
    float w00, w01, w10, w11;
    const __half *c00, *c01, *c10, *c11;
};

__device__ __forceinline__ Corners corner_params(
    const float* __restrict__ ob, const __half* __restrict__ xb,
    int ky, int kx, int p)
{
    const int ho = p >> 6, wo = p & 63;
    float py = (float)(ho - 1 + ky) + __ldg(ob + p);
    float px = (float)(wo - 1 + kx) + __ldg(ob + P_ + p);

    float y0f = floorf(py), x0f = floorf(px);
    float ly = py - y0f, lx = px - x0f;
    float hy = 1.0f - ly, hx = 1.0f - lx;
    int y0 = (int)y0f, x0 = (int)x0f;
    int y1 = y0 + 1,   x1 = x0 + 1;

    bool vy0 = ((unsigned)y0 < (unsigned)H_);
    bool vy1 = ((unsigned)y1 < (unsigned)H_);
    bool vx0 = ((unsigned)x0 < (unsigned)W_);
    bool vx1 = ((unsigned)x1 < (unsigned)W_);

    int cy0 = min(max(y0, 0), H_ - 1);
    int cy1 = min(max(y1, 0), H_ - 1);
    int cx0 = min(max(x0, 0), W_ - 1);
    int cx1 = min(max(x1, 0), W_ - 1);

    Corners cp;
    cp.w00 = (vy0 && vx0) ? hy * hx : 0.0f;
    cp.w01 = (vy0 && vx1) ? hy * lx : 0.0f;
    cp.w10 = (vy1 && vx0) ? ly * hx : 0.0f;
    cp.w11 = (vy1 && vx1) ? ly * lx : 0.0f;
    cp.c00 = xb + (size_t)(cy0 * W_ + cx0) * C_;
    cp.c01 = xb + (size_t)(cy0 * W_ + cx1) * C_;
    cp.c10 = xb + (size_t)(cy1 * W_ + cx0) * C_;
    cp.c11 = xb + (size_t)(cy1 * W_ + cx1) * C_;
    return cp;
}

__device__ __forceinline__ uint4 bilin_combine(const Corners& cp,
        uint4 a00, uint4 a01, uint4 a10, uint4 a11)
{
    union { __half2 h[4]; uint4 v; } o;
    const __half2* h00 = (const __half2*)&a00;
    const __half2* h01 = (const __half2*)&a01;
    const __half2* h10 = (const __half2*)&a10;
    const __half2* h11 = (const __half2*)&a11;
    #pragma unroll
    for (int j = 0; j < 4; ++j) {
        float2 f00 = __half22float2(h00[j]);
        float2 f01 = __half22float2(h01[j]);
        float2 f10 = __half22float2(h10[j]);
        float2 f11 = __half22float2(h11[j]);
        float2 r;
        r.x = cp.w00 * f00.x + cp.w01 * f01.x + cp.w10 * f10.x + cp.w11 * f11.x;
        r.y = cp.w00 * f00.y + cp.w01 * f01.y + cp.w10 * f10.y + cp.w11 * f11.y;
        o.h[j] = __float22half2_rn(r);
    }
    return o.v;
}

__global__ __launch_bounds__(256)
void im2col_k(const float* __restrict__ off)
{
    const int lane = threadIdx.x & 31;
    const int wib  = threadIdx.x >> 5;        // 0..7
    const int bid  = blockIdx.x;              // N*K*P/16 = 18432 blocks
    const int p0   = (bid & 255) * 16;
    const int k    = (bid >> 8) % 9;
    const int n    = bid / (256 * 9);
    const int ky   = k / 3, kx = k % 3;

    const int pA = p0 + wib;
    const int pB = p0 + 8 + wib;

    const float* ob = off + ((size_t)n * (2 * K_) + k * 2) * P_;
    const __half* xb = g_xh + ((size_t)n << 20);   // n * P_ * C_

    Corners ca = corner_params(ob, xb, ky, kx, pA);
    Corners cb = corner_params(ob, xb, ky, kx, pB);

    uint4 a00 = __ldg((const uint4*)ca.c00 + lane);
    uint4 a01 = __ldg((const uint4*)ca.c01 + lane);
    uint4 a10 = __ldg((const uint4*)ca.c10 + lane);
    uint4 a11 = __ldg((const uint4*)ca.c11 + lane);
    uint4 b00 = __ldg((const uint4*)cb.c00 + lane);
    uint4 b01 = __ldg((const uint4*)cb.c01 + lane);
    uint4 b10 = __ldg((const uint4*)cb.c10 + lane);
    uint4 b11 = __ldg((const uint4*)cb.c11 + lane);

    uint4 ra = bilin_combine(ca, a00, a01, a10, a11);
    uint4 rb = bilin_combine(cb, b00, b01, b10, b11);

    *(uint4*)(g_ch + ((size_t)(n * P_ + pA)) * CK_ + k * 256 + lane * 8) = ra;
    *(uint4*)(g_ch + ((size_t)(n * P_ + pB)) * CK_ + k * 256 + lane * 8) = rb;
}

// ---------------------------------------------------------------------------
// Kernel 2: fp16 mma.sync GEMM (R10-exact body).
// CTA tile 128 cout x 128 pixels, 8 warps of 64x32.
// K-chunk 64, 3-stage cp.async pipeline, one barrier per chunk.
// 110.6 KB smem, 2 CTAs/SM.
// ---------------------------------------------------------------------------
#define PITCH     144           // 128B data + 16B pad -> conflict-free ldmatrix
#define A_OFF     0
#define B_OFF     18432         // A: 128 rows * 144
#define STAGE     36864         // + B: 128 rows * 144
#define NSTAGE    3
#define SMEM_TOTAL (NSTAGE * STAGE)   // 110592 B

__device__ __forceinline__ void load_stage(uint32_t st, int chunk,
                                           int cout0, int n, int p0, int tid)
{
    const size_t cb = (size_t)chunk * 128;       // byte offset in 4608 B row
    #pragma unroll
    for (int i = 0; i < 8; ++i) {
        int idx = tid + i * 256;                 // 0..2047
        int region = idx >> 10;                  // 0=A(weights), 1=B(cols)
        int r   = idx & 1023;
        int row = r >> 3;                        // 0..127
        int c16 = (r & 7) * 16;                  // 0..112
        if (region == 0) {
            cp16(st + A_OFF + row * PITCH + c16,
                 (const char*)g_wh + (size_t)(cout0 + row) * (CK_ * 2) + cb + c16);
        } else {
            cp16(st + B_OFF + row * PITCH + c16,
                 (const char*)g_ch + ((size_t)(n * P_ + p0 + row)) * (CK_ * 2) + cb + c16);
        }
    }
}

__global__ __launch_bounds__(256, 2)
void gemm_k(const float* __restrict__ bias, float* __restrict__ out)
{
    extern __shared__ __align__(128) char smem[];
    const uint32_t sb = smem_to_u32(smem);

    const int tid    = threadIdx.x;
    const int lane   = tid & 31;
    const int wid    = tid >> 5;
    const int warp_m = wid & 1;       // 64-cout half
    const int warp_n = wid >> 1;      // 32-pixel quarter

    const int cout0 = blockIdx.x * 128;
    const int p0    = blockIdx.y * 128;
    const int n     = blockIdx.z;

    float d[4][4][4];
    #pragma unroll
    for (int mi = 0; mi < 4; ++mi)
        #pragma unroll
        for (int ni = 0; ni < 4; ++ni)
            #pragma unroll
            for (int j = 0; j < 4; ++j) d[mi][ni][j] = 0.0f;

    #pragma unroll
    for (int s = 0; s < NSTAGE - 1; ++s) {
        load_stage(sb + s * STAGE, s, cout0, n, p0, tid);
        cp_commit();
    }

    const int a_row = (lane & 15);
    const int a_c16 = (lane >> 4) << 4;
    const int b_row = (lane & 7) + ((lane >> 4) << 3);
    const int b_c16 = ((lane >> 3) & 1) << 4;

    int stage_id = 0;   // ring index of current chunk's stage
    for (int c = 0; c < NCHUNK; ++c) {
        cp_wait<NSTAGE - 2>();
        __syncthreads();

        if (c + NSTAGE - 1 < NCHUNK) {
            int pf = stage_id + (NSTAGE - 1);
            if (pf >= NSTAGE) pf -= NSTAGE;
            load_stage(sb + pf * STAGE, c + NSTAGE - 1, cout0, n, p0, tid);
        }
        cp_commit();

        const uint32_t st = sb + stage_id * STAGE;
        if (++stage_id == NSTAGE) stage_id = 0;

        #pragma unroll
        for (int s = 0; s < 4; ++s) {           // four k16 steps per chunk
            uint32_t ah[4][4];
            #pragma unroll
            for (int mi = 0; mi < 4; ++mi)
                ldsm4(ah[mi], st + A_OFF
                      + (warp_m * 64 + mi * 16 + a_row) * PITCH + s * 32 + a_c16);
            uint32_t bhf[2][4];
            #pragma unroll
            for (int np = 0; np < 2; ++np)
                ldsm4(bhf[np], st + B_OFF
                      + (warp_n * 32 + np * 16 + b_row) * PITCH + s * 32 + b_c16);
            #pragma unroll
            for (int mi = 0; mi < 4; ++mi)
                #pragma unroll
                for (int ni = 0; ni < 4; ++ni) {
                    const int np = ni >> 1, sub = (ni & 1) * 2;
                    mma16816h(d[mi][ni], ah[mi], bhf[np][sub], bhf[np][sub + 1]);
                }
        }
    }

    // epilogue: D fragment (row=cout, col=pixel) -> out[n][cout][p] + bias
    const int gr = lane >> 2;
    const int gc = (lane & 3) * 2;
    #pragma unroll
    for (int mi = 0; mi < 4; ++mi) {
        const int cout = cout0 + warp_m * 64 + mi * 16 + gr;
        const float bv0 = __ldg(bias + cout);
        const float bv1 = __ldg(bias + cout + 8);
        float* base = out + ((size_t)n * COUT_ + cout) * P_;
        #pragma unroll
        for (int ni = 0; ni < 4; ++ni) {
            const int px = p0 + warp_n * 32 + ni * 8 + gc;
            float2 v0 = make_float2(d[mi][ni][0] + bv0, d[mi][ni][1] + bv0);
            float2 v1 = make_float2(d[mi][ni][2] + bv1, d[mi][ni][3] + bv1);
            *(float2*)(base + px)          = v0;
            *(float2*)(base + 8 * P_ + px) = v1;
        }
    }
}

// ---------------------------------------------------------------------------
extern "C" void kernel_launch(void* const* d_in, const int* in_sizes, int n_in,
                              void* d_out, int out_size)
{
    const float* x    = (const float*)d_in[0];
    const float* off  = (const float*)d_in[1];
    const float* wgt  = (const float*)d_in[2];
    const float* bias = (const float*)d_in[3];
    float* out = (float*)d_out;

    static bool attr_set = false;
    if (!attr_set) {
        cudaFuncSetAttribute(gemm_k, cudaFuncAttributeMaxDynamicSharedMemorySize,
                             SMEM_TOTAL);
        attr_set = true;
    }

    prep_k<<<4096 + (COUT_ * CK_ + 255) / 256, 256>>>(x, wgt);
    im2col_k<<<N_ * K_ * P_ / 16, 256>>>(off);

    dim3 grid(COUT_ / 128, P_ / 128, N_);   // (2, 32, 8) = 512 CTAs
    gemm_k<<<grid, 256, SMEM_TOTAL>>>(bias, out);
}

// round 16
// speedup vs baseline: 2.1645x; 1.0498x over previous
#include <cuda_runtime.h>
#include <cuda_fp16.h>
#include <cstdint>
#include <math.h>

#define N_    8
#define C_    256
#define H_    64
#define W_    64
#define K_    9
#define P_    4096          // 64*64
#define CK_   2304          // C_*K_
#define COUT_ 256
#define NCHUNK 36           // CK_/64

// ------------------------------- scratch ------------------------------------
__device__ __half g_xh[(size_t)N_ * P_ * C_];     // x NHWC fp16
__device__ __half g_ch[(size_t)N_ * P_ * CK_];    // cols, K-major [n][p][k*256+c]
__device__ __half g_wh[COUT_ * CK_];              // weights [cout][k*256+c]

// ---------------- small PTX helpers (family-agnostic only) ------------------
__device__ __forceinline__ uint32_t smem_to_u32(const void* p) {
    uint32_t a;
    asm("{ .reg .u64 t; cvta.to.shared.u64 t, %1; cvt.u32.u64 %0, t; }"
        : "=r"(a) : "l"(p));
    return a;
}
__device__ __forceinline__ void cp16(uint32_t dst, const void* src) {
    asm volatile("cp.async.cg.shared.global [%0], [%1], 16;"
                 :: "r"(dst), "l"(src));
}
__device__ __forceinline__ void cp_commit() {
    asm volatile("cp.async.commit_group;" ::: "memory");
}
template <int NN>
__device__ __forceinline__ void cp_wait() {
    asm volatile("cp.async.wait_group %0;" :: "n"(NN) : "memory");
}
__device__ __forceinline__ void ldsm4(uint32_t* r, uint32_t addr) {
    asm volatile("ldmatrix.sync.aligned.m8n8.x4.shared.b16 {%0,%1,%2,%3}, [%4];"
        : "=r"(r[0]), "=r"(r[1]), "=r"(r[2]), "=r"(r[3]) : "r"(addr));
}
__device__ __forceinline__ void mma16816h(float* d, const uint32_t* a,
                                          uint32_t b0, uint32_t b1) {
    asm volatile("mma.sync.aligned.m16n8k16.row.col.f32.f16.f16.f32 "
        "{%0,%1,%2,%3}, {%4,%5,%6,%7}, {%8,%9}, {%0,%1,%2,%3};"
        : "+f"(d[0]), "+f"(d[1]), "+f"(d[2]), "+f"(d[3])
        : "r"(a[0]), "r"(a[1]), "r"(a[2]), "r"(a[3]), "r"(b0), "r"(b1));
}

// ---------------------------------------------------------------------------
// Kernel P: fused prep. Blocks [0, 4096): x NCHW fp32 -> NHWC fp16 transpose.
// Blocks [4096, 6400): weight convert + reorder.
// ---------------------------------------------------------------------------
__global__ __launch_bounds__(256)
void prep_k(const float* __restrict__ x, const float* __restrict__ w) {
    const int bid = blockIdx.x;
    if (bid < 4096) {                    // ---- nhwc transpose ----
        __shared__ float sm[64][33];
        const int s0 = (bid & 127) * 32;
        const int c0 = ((bid >> 7) & 3) * 64;
        const int n  = bid >> 9;
        const int tx = threadIdx.x & 31;
        const int ty = threadIdx.x >> 5;

        #pragma unroll
        for (int i = 0; i < 8; ++i) {
            int c = i * 8 + ty;
            sm[c][tx] = x[((size_t)n * C_ + c0 + c) * P_ + s0 + tx];
        }
        __syncthreads();
        #pragma unroll
        for (int i = 0; i < 4; ++i) {
            int s = i * 8 + ty;
            __half2 h = __floats2half2_rn(sm[2 * tx][s], sm[2 * tx + 1][s]);
            *(__half2*)(g_xh + ((size_t)(n * P_ + s0 + s)) * C_ + c0 + 2 * tx) = h;
        }
    } else {                             // ---- weight convert + reorder ----
        int o = (bid - 4096) * 256 + threadIdx.x;
        if (o >= COUT_ * CK_) return;
        int cout = o / CK_;
        int r    = o % CK_;
        int k    = r >> 8;
        int c    = r & 255;
        g_wh[o] = __float2half_rn(w[(size_t)cout * CK_ + c * 9 + k]);
    }
}

// ---------------------------------------------------------------------------
// Kernel 1: deformable im2col (batched, MLP-8; HFMA2 bilinear combine).
// ---------------------------------------------------------------------------
struct Corners {
    __half2 W00, W01, W10, W11;          // bilinear weights broadcast to half2
    const __half *c00, *c01, *c10, *c11;
};

__device__ __forceinline__ Corners corner_params(
    const float* __restrict__ ob, const __half* __restrict__ xb,
    int ky, int kx, int p)
{
    const int ho = p >> 6, wo = p & 63;
    float py = (float)(ho - 1 + ky) + __ldg(ob + p);
    float px = (float)(wo - 1 + kx) + __ldg(ob + P_ + p);

    float y0f = floorf(py), x0f = floorf(px);
    float ly = py - y0f, lx = px - x0f;
    float hy = 1.0f - ly, hx = 1.0f - lx;
    int y0 = (int)y0f, x0 = (int)x0f;
    int y1 = y0 + 1,   x1 = x0 + 1;

    bool vy0 = ((unsigned)y0 < (unsigned)H_);
    bool vy1 = ((unsigned)y1 < (unsigned)H_);
    bool vx0 = ((unsigned)x0 < (unsigned)W_);
    bool vx1 = ((unsigned)x1 < (unsigned)W_);

    int cy0 = min(max(y0, 0), H_ - 1);
    int cy1 = min(max(y1, 0), H_ - 1);
    int cx0 = min(max(x0, 0), W_ - 1);
    int cx1 = min(max(x1, 0), W_ - 1);

    Corners cp;
    cp.W00 = __float2half2_rn((vy0 && vx0) ? hy * hx : 0.0f);
    cp.W01 = __float2half2_rn((vy0 && vx1) ? hy * lx : 0.0f);
    cp.W10 = __float2half2_rn((vy1 && vx0) ? ly * hx : 0.0f);
    cp.W11 = __float2half2_rn((vy1 && vx1) ? ly * lx : 0.0f);
    cp.c00 = xb + (size_t)(cy0 * W_ + cx0) * C_;
    cp.c01 = xb + (size_t)(cy0 * W_ + cx1) * C_;
    cp.c10 = xb + (size_t)(cy1 * W_ + cx0) * C_;
    cp.c11 = xb + (size_t)(cy1 * W_ + cx1) * C_;
    return cp;
}

__device__ __forceinline__ uint4 bilin_combine(const Corners& cp,
        uint4 a00, uint4 a01, uint4 a10, uint4 a11)
{
    union { __half2 h[4]; uint4 v; } o;
    const __half2* h00 = (const __half2*)&a00;
    const __half2* h01 = (const __half2*)&a01;
    const __half2* h10 = (const __half2*)&a10;
    const __half2* h11 = (const __half2*)&a11;
    #pragma unroll
    for (int j = 0; j < 4; ++j) {
        __half2 r = __hmul2(cp.W00, h00[j]);
        r = __hfma2(cp.W01, h01[j], r);
        r = __hfma2(cp.W10, h10[j], r);
        r = __hfma2(cp.W11, h11[j], r);
        o.h[j] = r;
    }
    return o.v;
}

__global__ __launch_bounds__(256)
void im2col_k(const float* __restrict__ off)
{
    const int lane = threadIdx.x & 31;
    const int wib  = threadIdx.x >> 5;        // 0..7
    const int bid  = blockIdx.x;              // N*K*P/16 = 18432 blocks
    const int p0   = (bid & 255) * 16;
    const int k    = (bid >> 8) % 9;
    const int n    = bid / (256 * 9);
    const int ky   = k / 3, kx = k % 3;

    const int pA = p0 + wib;
    const int pB = p0 + 8 + wib;

    const float* ob = off + ((size_t)n * (2 * K_) + k * 2) * P_;
    const __half* xb = g_xh + ((size_t)n << 20);   // n * P_ * C_

    Corners ca = corner_params(ob, xb, ky, kx, pA);
    Corners cb = corner_params(ob, xb, ky, kx, pB);

    uint4 a00 = __ldg((const uint4*)ca.c00 + lane);
    uint4 a01 = __ldg((const uint4*)ca.c01 + lane);
    uint4 a10 = __ldg((const uint4*)ca.c10 + lane);
    uint4 a11 = __ldg((const uint4*)ca.c11 + lane);
    uint4 b00 = __ldg((const uint4*)cb.c00 + lane);
    uint4 b01 = __ldg((const uint4*)cb.c01 + lane);
    uint4 b10 = __ldg((const uint4*)cb.c10 + lane);
    uint4 b11 = __ldg((const uint4*)cb.c11 + lane);

    uint4 ra = bilin_combine(ca, a00, a01, a10, a11);
    uint4 rb = bilin_combine(cb, b00, b01, b10, b11);

    *(uint4*)(g_ch + ((size_t)(n * P_ + pA)) * CK_ + k * 256 + lane * 8) = ra;
    *(uint4*)(g_ch + ((size_t)(n * P_ + pB)) * CK_ + k * 256 + lane * 8) = rb;
}

// ---------------------------------------------------------------------------
// Kernel 2: fp16 mma.sync GEMM (R10-exact body).
// CTA tile 128 cout x 128 pixels, 8 warps of 64x32.
// K-chunk 64, 3-stage cp.async pipeline, one barrier per chunk.
// 110.6 KB smem, 2 CTAs/SM.
// ---------------------------------------------------------------------------
#define PITCH     144           // 128B data + 16B pad -> conflict-free ldmatrix
#define A_OFF     0
#define B_OFF     18432         // A: 128 rows * 144
#define STAGE     36864         // + B: 128 rows * 144
#define NSTAGE    3
#define SMEM_TOTAL (NSTAGE * STAGE)   // 110592 B

__device__ __forceinline__ void load_stage(uint32_t st, int chunk,
                                           int cout0, int n, int p0, int tid)
{
    const size_t cb = (size_t)chunk * 128;       // byte offset in 4608 B row
    #pragma unroll
    for (int i = 0; i < 8; ++i) {
        int idx = tid + i * 256;                 // 0..2047
        int region = idx >> 10;                  // 0=A(weights), 1=B(cols)
        int r   = idx & 1023;
        int row = r >> 3;                        // 0..127
        int c16 = (r & 7) * 16;                  // 0..112
        if (region == 0) {
            cp16(st + A_OFF + row * PITCH + c16,
                 (const char*)g_wh + (size_t)(cout0 + row) * (CK_ * 2) + cb + c16);
        } else {
            cp16(st + B_OFF + row * PITCH + c16,
                 (const char*)g_ch + ((size_t)(n * P_ + p0 + row)) * (CK_ * 2) + cb + c16);
        }
    }
}

__global__ __launch_bounds__(256, 2)
void gemm_k(const float* __restrict__ bias, float* __restrict__ out)
{
    extern __shared__ __align__(128) char smem[];
    const uint32_t sb = smem_to_u32(smem);

    const int tid    = threadIdx.x;
    const int lane   = tid & 31;
    const int wid    = tid >> 5;
    const int warp_m = wid & 1;       // 64-cout half
    const int warp_n = wid >> 1;      // 32-pixel quarter

    const int cout0 = blockIdx.x * 128;
    const int p0    = blockIdx.y * 128;
    const int n     = blockIdx.z;

    float d[4][4][4];
    #pragma unroll
    for (int mi = 0; mi < 4; ++mi)
        #pragma unroll
        for (int ni = 0; ni < 4; ++ni)
            #pragma unroll
            for (int j = 0; j < 4; ++j) d[mi][ni][j] = 0.0f;

    #pragma unroll
    for (int s = 0; s < NSTAGE - 1; ++s) {
        load_stage(sb + s * STAGE, s, cout0, n, p0, tid);
        cp_commit();
    }

    const int a_row = (lane & 15);
    const int a_c16 = (lane >> 4) << 4;
    const int b_row = (lane & 7) + ((lane >> 4) << 3);
    const int b_c16 = ((lane >> 3) & 1) << 4;

    int stage_id = 0;   // ring index of current chunk's stage
    for (int c = 0; c < NCHUNK; ++c) {
        cp_wait<NSTAGE - 2>();
        __syncthreads();

        if (c + NSTAGE - 1 < NCHUNK) {
            int pf = stage_id + (NSTAGE - 1);
            if (pf >= NSTAGE) pf -= NSTAGE;
            load_stage(sb + pf * STAGE, c + NSTAGE - 1, cout0, n, p0, tid);
        }
        cp_commit();

        const uint32_t st = sb + stage_id * STAGE;
        if (++stage_id == NSTAGE) stage_id = 0;

        #pragma unroll
        for (int s = 0; s < 4; ++s) {           // four k16 steps per chunk
            uint32_t ah[4][4];
            #pragma unroll
            for (int mi = 0; mi < 4; ++mi)
                ldsm4(ah[mi], st + A_OFF
                      + (warp_m * 64 + mi * 16 + a_row) * PITCH + s * 32 + a_c16);
            uint32_t bhf[2][4];
            #pragma unroll
            for (int np = 0; np < 2; ++np)
                ldsm4(bhf[np], st + B_OFF
                      + (warp_n * 32 + np * 16 + b_row) * PITCH + s * 32 + b_c16);
            #pragma unroll
            for (int mi = 0; mi < 4; ++mi)
                #pragma unroll
                for (int ni = 0; ni < 4; ++ni) {
                    const int np = ni >> 1, sub = (ni & 1) * 2;
                    mma16816h(d[mi][ni], ah[mi], bhf[np][sub], bhf[np][sub + 1]);
                }
        }
    }

    // epilogue: D fragment (row=cout, col=pixel) -> out[n][cout][p] + bias
    const int gr = lane >> 2;
    const int gc = (lane & 3) * 2;
    #pragma unroll
    for (int mi = 0; mi < 4; ++mi) {
        const int cout = cout0 + warp_m * 64 + mi * 16 + gr;
        const float bv0 = __ldg(bias + cout);
        const float bv1 = __ldg(bias + cout + 8);
        float* base = out + ((size_t)n * COUT_ + cout) * P_;
        #pragma unroll
        for (int ni = 0; ni < 4; ++ni) {
            const int px = p0 + warp_n * 32 + ni * 8 + gc;
            float2 v0 = make_float2(d[mi][ni][0] + bv0, d[mi][ni][1] + bv0);
            float2 v1 = make_float2(d[mi][ni][2] + bv1, d[mi][ni][3] + bv1);
            *(float2*)(base + px)          = v0;
            *(float2*)(base + 8 * P_ + px) = v1;
        }
    }
}

// ---------------------------------------------------------------------------
extern "C" void kernel_launch(void* const* d_in, const int* in_sizes, int n_in,
                              void* d_out, int out_size)
{
    const float* x    = (const float*)d_in[0];
    const float* off  = (const float*)d_in[1];
    const float* wgt  = (const float*)d_in[2];
    const float* bias = (const float*)d_in[3];
    float* out = (float*)d_out;

    static bool attr_set = false;
    if (!attr_set) {
        cudaFuncSetAttribute(gemm_k, cudaFuncAttributeMaxDynamicSharedMemorySize,
                             SMEM_TOTAL);
        attr_set = true;
    }

    prep_k<<<4096 + (COUT_ * CK_ + 255) / 256, 256>>>(x, wgt);
    im2col_k<<<N_ * K_ * P_ / 16, 256>>>(off);

    dim3 grid(COUT_ / 128, P_ / 128, N_);   // (2, 32, 8) = 512 CTAs
    gemm_k<<<grid, 256, SMEM_TOTAL>>>(bias, out);
}